// round 15
// baseline (speedup 1.0000x reference)
#include <cuda_runtime.h>
#include <cuda_fp16.h>
#include <math.h>
#include <stdint.h>

#define BV    64
#define SV    512
#define DIMV  1024
#define COVV  256
#define ROWS  (BV*SV)
#define G3    768
#define XW    2049

// ---------------- scratch ----------------------------------------------------
__device__ __half g_rz[(size_t)ROWS * 512];
__device__ __half g_xn[(size_t)ROWS * 256];
__device__ __half g_hn[(size_t)ROWS * 256];
__device__ __half g_ctxh[(size_t)ROWS * DIMV];
__device__ __half g_covh[(size_t)ROWS * COVV];
__device__ float g_target[BV * DIMV];
__device__ float g_tpp[8 * BV * COVV];        // tproj partials per d-chunk
__device__ float g_hB[BV * G3];
__device__ __half g_wihAh[(size_t)G3 * DIMV];
__device__ float  g_wihAf[(size_t)G3 * DIMV];
__device__ float g_wihH[(size_t)G3 * DIMV];
__device__ __half g_whhh[(size_t)G3 * COVV];
__device__ float g_wcovT[(size_t)COVV * DIMV];
__device__ __half g_M2h[(size_t)G3 * COVV];
__device__ float g_wihC[G3];
__device__ float g_bsum[G3];
__device__ float g_score[ROWS];
__device__ float g_attn[ROWS];
__device__ float g_cat[BV * 2 * DIMV];
__device__ float g_part[2490368];
__device__ int   g_maskmode;

#define P_TGT 0
#define P_HB  524288
#define P_M2  917504

// ---------------- PTX helpers -------------------------------------------------
__device__ __forceinline__ uint32_t smem_u32(const void* p) {
    uint32_t a;
    asm("{ .reg .u64 t; cvta.to.shared.u64 t, %1; cvt.u32.u64 %0, t; }" : "=r"(a) : "l"(p));
    return a;
}
__device__ __forceinline__ void cpasync16(uint32_t dst, const void* src) {
    asm volatile("cp.async.ca.shared.global [%0], [%1], 16;" :: "r"(dst), "l"(src));
}
#define CP_COMMIT() asm volatile("cp.async.commit_group;" ::: "memory")
#define CP_WAIT1()  asm volatile("cp.async.wait_group 1;" ::: "memory")

#define LDSM4(r0,r1,r2,r3,addr) \
    asm volatile("ldmatrix.sync.aligned.m8n8.x4.shared.b16 {%0,%1,%2,%3}, [%4];" \
        : "=r"(r0),"=r"(r1),"=r"(r2),"=r"(r3) : "r"(addr))

#define MMA16(d, a, b0v, b1v) \
    asm volatile("mma.sync.aligned.m16n8k16.row.col.f32.f16.f16.f32 " \
        "{%0,%1,%2,%3},{%4,%5,%6,%7},{%8,%9},{%0,%1,%2,%3};" \
        : "+f"((d)[0]),"+f"((d)[1]),"+f"((d)[2]),"+f"((d)[3]) \
        : "r"((a)[0]),"r"((a)[1]),"r"((a)[2]),"r"((a)[3]),"r"(b0v),"r"(b1v))

__device__ __forceinline__ uint32_t swz(uint32_t o) { return o ^ ((o >> 3) & 0x70u); }
__device__ __forceinline__ float sigmf(float x) { return 1.f / (1.f + __expf(-x)); }

// ---------------- fp16 GEMM machinery: 64-half K stages, SW128, seg list -------
#define TBYTES 16384u
struct Seg { const __half* A; int lda; const __half* B; int ldb; int n; };

__device__ __forceinline__ void load_stage_h(const __half* __restrict__ A, int lda,
                                             const __half* __restrict__ B, int ldb,
                                             uint32_t smb, int buf, int kloc,
                                             int row0, int tid)
{
    const uint32_t dA = smb + (uint32_t)buf * 2u * TBYTES;
    const uint32_t dB = dA + TBYTES;
    #pragma unroll
    for (int it = 0; it < 4; ++it) {
        const int id = it * 256 + tid;
        const int r = id >> 3, q = id & 7;
        const uint32_t so = swz((uint32_t)(r * 128 + q * 16));
        cpasync16(dA + so, A + (size_t)(row0 + r) * lda + (size_t)kloc * 64 + q * 8);
        cpasync16(dB + so, B + (size_t)r * ldb + (size_t)kloc * 64 + q * 8);
    }
    CP_COMMIT();
}

__device__ __forceinline__ void seg_fetch(const Seg* segs, int nseg, int buf, int s,
                                          uint32_t smb, int row0, int tid)
{
    int t = s;
    #pragma unroll 1
    for (int g = 0; g < nseg; ++g) {
        if (t < segs[g].n) {
            load_stage_h(segs[g].A, segs[g].lda, segs[g].B, segs[g].ldb,
                         smb, buf, t, row0, tid);
            return;
        }
        t -= segs[g].n;
    }
}

__device__ void mma_pass(const Seg* segs, int nseg, int row0, uint32_t smb,
                         float acc[4][4][4])
{
    const int tid = threadIdx.x, lane = tid & 31, wid = tid >> 5;
    const int wm = wid & 1, wn = wid >> 1;
    const int t8 = lane >> 3, r8 = lane & 7;
    uint32_t abase[4], bbase[2];
    #pragma unroll
    for (int m = 0; m < 4; ++m)
        abase[m] = (uint32_t)((wm * 64 + m * 16 + (t8 & 1) * 8 + r8) * 128 + (t8 >> 1) * 16);
    #pragma unroll
    for (int p = 0; p < 2; ++p)
        bbase[p] = (uint32_t)((wn * 32 + p * 16 + (t8 & 1) * 8 + r8) * 128 + (t8 >> 1) * 16);

    #pragma unroll
    for (int m = 0; m < 4; ++m)
        #pragma unroll
        for (int n = 0; n < 4; ++n)
            #pragma unroll
            for (int i = 0; i < 4; ++i) acc[m][n][i] = 0.f;

    int S = 0;
    for (int g = 0; g < nseg; ++g) S += segs[g].n;

    seg_fetch(segs, nseg, 0, 0, smb, row0, tid);
    seg_fetch(segs, nseg, 1, 1, smb, row0, tid);

    #pragma unroll 1
    for (int kt = 0; kt < S; ++kt) {
        CP_WAIT1();
        __syncthreads();
        if (kt + 2 < S) seg_fetch(segs, nseg, (kt + 2) % 3, kt + 2, smb, row0, tid);
        const uint32_t stg = smb + (uint32_t)(kt % 3) * 2u * TBYTES;

        #pragma unroll
        for (int ks = 0; ks < 4; ++ks) {
            uint32_t ah[4][4], bh[4][2];
            #pragma unroll
            for (int m = 0; m < 4; ++m)
                LDSM4(ah[m][0], ah[m][1], ah[m][2], ah[m][3],
                      stg + swz(abase[m] + (uint32_t)ks * 32u));
            #pragma unroll
            for (int p = 0; p < 2; ++p) {
                uint32_t x0, x1, x2, x3;
                LDSM4(x0, x1, x2, x3, stg + TBYTES + swz(bbase[p] + (uint32_t)ks * 32u));
                bh[2 * p + 0][0] = x0; bh[2 * p + 0][1] = x2;
                bh[2 * p + 1][0] = x1; bh[2 * p + 1][1] = x3;
            }
            #pragma unroll
            for (int m = 0; m < 4; ++m)
                #pragma unroll
                for (int n = 0; n < 4; ++n)
                    MMA16(acc[m][n], ah[m], bh[n][0], bh[n][1]);
        }
    }
}

#define FOR_ELEMS(...)                                                          \
    {                                                                           \
        const int g2 = lane >> 2, tg = lane & 3;                                \
        _Pragma("unroll")                                                       \
        for (int m = 0; m < 4; ++m)                                             \
        _Pragma("unroll")                                                       \
        for (int h2 = 0; h2 < 2; ++h2) {                                        \
            const int row = row0 + wm * 64 + m * 16 + h2 * 8 + g2;              \
            const int bI = row >> 9;                                            \
            const float at = g_attn[row];                                       \
            (void)bI; (void)at;                                                 \
            _Pragma("unroll")                                                   \
            for (int nn = 0; nn < 4; ++nn) {                                    \
                const int cl = wn * 32 + nn * 8 + 2 * tg;                       \
                float x0 = acc[m][nn][h2 * 2 + 0];                              \
                float x1 = acc[m][nn][h2 * 2 + 1];                              \
                __VA_ARGS__                                                     \
            }                                                                   \
        }                                                                       \
    }

// ---------------- split-K fp32 SGEMM core --------------------------------------
__device__ void sgemm_core(
    const float* __restrict__ X, int ldx,
    const float* __restrict__ W, int ldw,
    int k0, int k1, int row0, int col0, int N,
    float* __restrict__ partz, float* sm)
{
    float* Xs = sm;
    float* Ws = sm + 1088;
    const int tid = threadIdx.x;
    const int tr = tid >> 5, tc = tid & 31;
    float acc[8][4];
    #pragma unroll
    for (int i = 0; i < 8; ++i)
        #pragma unroll
        for (int j = 0; j < 4; ++j) acc[i][j] = 0.f;

    const int xr = tid >> 2, xk = (tid & 3) * 4;
    for (int kt = k0; kt < k1; kt += 16) {
        float4 xv = *(const float4*)(X + (size_t)(row0 + xr) * ldx + kt + xk);
        Xs[(xk+0)*68+xr] = xv.x; Xs[(xk+1)*68+xr] = xv.y;
        Xs[(xk+2)*68+xr] = xv.z; Xs[(xk+3)*68+xr] = xv.w;
        #pragma unroll
        for (int w2 = 0; w2 < 2; ++w2) {
            const int r = xr + w2 * 64;
            float4 wv = *(const float4*)(W + (size_t)(col0 + r) * ldw + kt + xk);
            Ws[(xk+0)*132+r] = wv.x; Ws[(xk+1)*132+r] = wv.y;
            Ws[(xk+2)*132+r] = wv.z; Ws[(xk+3)*132+r] = wv.w;
        }
        __syncthreads();
        #pragma unroll
        for (int kk = 0; kk < 16; ++kk) {
            float a[8], bb[4];
            #pragma unroll
            for (int i = 0; i < 8; ++i) a[i] = Xs[kk*68 + tr * 8 + i];
            #pragma unroll
            for (int j = 0; j < 4; ++j) bb[j] = Ws[kk*132 + tc * 4 + j];
            #pragma unroll
            for (int i = 0; i < 8; ++i)
                #pragma unroll
                for (int j = 0; j < 4; ++j) acc[i][j] += a[i] * bb[j];
        }
        __syncthreads();
    }
    #pragma unroll
    for (int i = 0; i < 8; ++i)
        *(float4*)(partz + (size_t)(row0 + tr * 8 + i) * N + col0 + tc * 4)
            = make_float4(acc[i][0], acc[i][1], acc[i][2], acc[i][3]);
}

__global__ void __launch_bounds__(256) sgemm3_kernel(
    const float* __restrict__ h, const float* __restrict__ W_in)
{
    extern __shared__ float sm[];
    const int bid = blockIdx.x;
    if (bid < 64) {
        const int bx = bid & 7, bz = bid >> 3;
        sgemm_core(h, DIMV, W_in, DIMV, bz * 128, bz * 128 + 128,
                   0, bx * 128, DIMV, g_part + P_TGT + (size_t)bz * BV * DIMV, sm);
    } else if (bid < 112) {
        const int r = bid - 64, bx = r % 6, bz = r / 6;
        sgemm_core(h, DIMV, g_wihH, DIMV, bz * 128, bz * 128 + 128,
                   0, bx * 128, G3, g_part + P_HB + (size_t)bz * BV * G3, sm);
    } else {
        const int r = bid - 112;
        const int bx = r & 1, by = (r >> 1) % 12, bz = r / 24;
        sgemm_core(g_wihAf, DIMV, g_wcovT, DIMV, bz * 128, bz * 128 + 128,
                   by * 64, bx * 128, COVV, g_part + P_M2 + (size_t)bz * G3 * COVV, sm);
    }
}

// ---------------- reduce3: target+tproj partials (8) | hB (48) | M2 (192) -------
__global__ void reduce3_kernel()
{
    __shared__ float tgt[64 * 128];
    const int bid = blockIdx.x, tid = threadIdx.x;
    if (bid < 8) {
        const int z = bid, d0 = z * 128;
        // reduce target chunk into smem + write g_target
        for (int idx = tid; idx < 8192; idx += 256) {
            const int b = idx >> 7, d = idx & 127;
            float s = 0.f;
            #pragma unroll
            for (int z2 = 0; z2 < 8; ++z2)
                s += g_part[P_TGT + z2 * 65536 + b * 1024 + d0 + d];
            tgt[b * 128 + d] = s;
            g_target[b * 1024 + d0 + d] = s;
        }
        __syncthreads();
        // tproj partial: thread = c, acc over 64 batches, K = this 128-d chunk
        const int c = tid;
        float acc[64];
        #pragma unroll
        for (int b = 0; b < 64; ++b) acc[b] = 0.f;
        const float* wr = g_wcovT + (size_t)c * DIMV + d0;
        #pragma unroll 1
        for (int ch = 0; ch < 4; ++ch) {
            float4 w4[8];
            #pragma unroll
            for (int i = 0; i < 8; ++i) w4[i] = *(const float4*)(wr + ch * 32 + i * 4);
            #pragma unroll 4
            for (int b = 0; b < 64; ++b) {
                float s = 0.f;
                #pragma unroll
                for (int i = 0; i < 8; ++i) {
                    float4 t4 = *(const float4*)&tgt[b * 128 + ch * 32 + i * 4];
                    s += t4.x * w4[i].x + t4.y * w4[i].y + t4.z * w4[i].z + t4.w * w4[i].w;
                }
                acc[b] += s;
            }
        }
        #pragma unroll 4
        for (int b = 0; b < 64; ++b)
            g_tpp[(z * 64 + b) * COVV + c] = acc[b];
        return;
    }
    if (bid < 56) {
        const int i = (bid - 8) * 256 + tid;          // 12288 f4 of hB
        float4 s = make_float4(0.f, 0.f, 0.f, 0.f);
        for (int z = 0; z < 8; ++z) {
            float4 p = *(const float4*)(g_part + P_HB + (size_t)z * 49152 + i * 4);
            s.x += p.x; s.y += p.y; s.z += p.z; s.w += p.w;
        }
        *(float4*)(g_hB + i * 4) = s;
        return;
    }
    {
        const int i = (bid - 56) * 256 + tid;         // 49152 f4 of M2
        float4 s = make_float4(0.f, 0.f, 0.f, 0.f);
        for (int z = 0; z < 8; ++z) {
            float4 p = *(const float4*)(g_part + P_M2 + (size_t)z * 196608 + i * 4);
            s.x += p.x; s.y += p.y; s.z += p.z; s.w += p.w;
        }
        __half2 h0 = __floats2half2_rn(s.x, s.y);
        __half2 h1 = __floats2half2_rn(s.z, s.w);
        uint2 o; o.x = *(uint32_t*)&h0; o.y = *(uint32_t*)&h1;
        *(uint2*)(g_M2h + (size_t)i * 4) = o;
    }
}

// ---------------- prologue: mask detect | repack | cov->fp16 ---------------------
__global__ void prep_kernel(const unsigned int* __restrict__ mask,
                            const float* __restrict__ w_ih,
                            const float* __restrict__ w_hh,
                            const float* __restrict__ W_cov,
                            const float* __restrict__ b_cov,
                            const float* __restrict__ b_ih,
                            const float* __restrict__ b_hh,
                            const float* __restrict__ cov)
{
    const int bid = blockIdx.x, tid = threadIdx.x;
    if (bid == 0) {
        __shared__ int notint, notfloat;
        if (tid == 0) { notint = 0; notfloat = 0; }
        __syncthreads();
        int li = 0, lf = 0;
        for (int i = tid; i < 8192; i += 256) {
            unsigned v = mask[i];
            if (v > 1u) li = 1;
            if (v != 0u && v != 0x3F800000u) lf = 1;
        }
        if (li) notint = 1;
        if (lf) notfloat = 1;
        __syncthreads();
        if (tid == 0) g_maskmode = (!notint) ? 0 : ((!notfloat) ? 1 : 2);
        return;
    }
    if (bid <= 1024) {
        const int j = bid - 1;
        if (j < G3) {
            __shared__ float red[256];
            float pa = 0.f;
            for (int k = tid; k < DIMV; k += 256) {
                float a = w_ih[(size_t)j * XW + k];
                __half ah = __float2half_rn(a);
                g_wihAh[(size_t)j * DIMV + k] = ah;
                g_wihAf[(size_t)j * DIMV + k] = __half2float(ah);
                g_wihH[(size_t)j * DIMV + k] = w_ih[(size_t)j * XW + DIMV + k];
                pa += a * b_cov[k];
            }
            if (tid < COVV)
                g_whhh[(size_t)j * COVV + tid] = __float2half_rn(w_hh[(size_t)j * COVV + tid]);
            red[tid] = pa; __syncthreads();
            for (int o = 128; o > 0; o >>= 1) { if (tid < o) red[tid] += red[tid + o]; __syncthreads(); }
            if (tid == 0) {
                float bs = red[0] + b_ih[j];
                if (j < 512) bs += b_hh[j];
                g_bsum[j] = bs;
                g_wihC[j] = w_ih[(size_t)j * XW + 2 * DIMV];
            }
        } else {
            const int c = j - G3;
            for (int d = tid; d < DIMV; d += 256)
                g_wcovT[(size_t)c * DIMV + d] = W_cov[(size_t)d * COVV + c];
        }
        return;
    }
    const int i = (bid - 1025) * 256 + tid;
    const size_t off = (size_t)i * 8;
    float4 a = *(const float4*)(cov + off);
    float4 b = *(const float4*)(cov + off + 4);
    __half2 h0 = __floats2half2_rn(a.x, a.y);
    __half2 h1 = __floats2half2_rn(a.z, a.w);
    __half2 h2 = __floats2half2_rn(b.x, b.y);
    __half2 h3 = __floats2half2_rn(b.z, b.w);
    uint4 o;
    o.x = *(uint32_t*)&h0; o.y = *(uint32_t*)&h1;
    o.z = *(uint32_t*)&h2; o.w = *(uint32_t*)&h3;
    *(uint4*)(g_covh + off) = o;
}

// ---------------- exact scores + fused ctx->fp16 (tpp summed inline) -------------
__global__ void score_kernel(const float* __restrict__ context,
                             const float* __restrict__ cov)
{
    const int r = blockIdx.x * 8 + (threadIdx.x >> 5);
    const int lane = threadIdx.x & 31;
    const int b = r >> 9;
    const float4* ct = (const float4*)(context + (size_t)r * DIMV);
    const float4* tg = (const float4*)(g_target + (size_t)b * DIMV);
    float s = 0.f;
    #pragma unroll
    for (int i = 0; i < 8; ++i) {
        float4 c4 = ct[lane + i * 32], t4 = tg[lane + i * 32];
        s += c4.x * t4.x + c4.y * t4.y + c4.z * t4.z + c4.w * t4.w;
        __half2 p0 = __floats2half2_rn(c4.x, c4.y);
        __half2 p1 = __floats2half2_rn(c4.z, c4.w);
        uint2 o; o.x = *(uint32_t*)&p0; o.y = *(uint32_t*)&p1;
        *(uint2*)(g_ctxh + (size_t)r * DIMV + (size_t)(lane + i * 32) * 4) = o;
    }
    const float4* cv = (const float4*)(cov + (size_t)r * COVV);
    #pragma unroll
    for (int i = 0; i < 2; ++i) {
        float4 c4 = cv[lane + i * 32];
        float4 t4 = make_float4(0.f, 0.f, 0.f, 0.f);
        #pragma unroll
        for (int z = 0; z < 8; ++z) {
            float4 p = *(const float4*)(g_tpp + ((size_t)(z * 64 + b) * COVV) + (lane + i * 32) * 4);
            t4.x += p.x; t4.y += p.y; t4.z += p.z; t4.w += p.w;
        }
        s += c4.x * t4.x + c4.y * t4.y + c4.z * t4.z + c4.w * t4.w;
    }
    #pragma unroll
    for (int o = 16; o; o >>= 1) s += __shfl_xor_sync(0xffffffffu, s, o);
    if (lane == 0) g_score[r] = s;
}

// ---------------- fused softmax + wc + aco + cat ---------------------------------
__global__ void __launch_bounds__(1024) softmax_fused(
    const void* __restrict__ mask,
    const float* __restrict__ h, const float* __restrict__ b_cov,
    float* __restrict__ out_attn)
{
    const int b = blockIdx.x, t = threadIdx.x;
    __shared__ float at[SV];
    __shared__ float red[SV];
    __shared__ float2 px[1024];
    __shared__ float wcs[DIMV];
    __shared__ float ac[COVV];

    const int mode = g_maskmode;
    float sc = 0.f; bool masked = false;
    if (t < SV) {
        const int idx = b * SV + t;
        if (mode == 0)      masked = ((const int*)mask)[idx] != 0;
        else if (mode == 1) masked = ((const float*)mask)[idx] != 0.0f;
        else                masked = ((const unsigned char*)mask)[idx] != 0;
        sc = masked ? -INFINITY : g_score[idx];
        red[t] = sc;
    }
    __syncthreads();
    for (int o = 256; o > 0; o >>= 1) {
        if (t < o) red[t] = fmaxf(red[t], red[t + o]);
        __syncthreads();
    }
    const float m = red[0];
    __syncthreads();
    float e = 0.f;
    if (t < SV) { e = masked ? 0.f : __expf(sc - m); red[t] = e; }
    __syncthreads();
    for (int o = 256; o > 0; o >>= 1) {
        if (t < o) red[t] += red[t + o];
        __syncthreads();
    }
    const float inv = 1.f / red[0];
    if (t < SV) {
        const float a = e * inv;
        at[t] = a;
        g_attn[b * SV + t] = a;
        out_attn[b * SV + t] = a;
    }
    __syncthreads();

    {
        const __half2* ctx2 = (const __half2*)(g_ctxh + (size_t)b * SV * DIMV);
        const int h2 = t & 511, grp = t >> 9;
        float2 acc = make_float2(0.f, 0.f);
        const int s0 = grp * 256;
        #pragma unroll 8
        for (int s = 0; s < 256; ++s) {
            float2 c = __half22float2(ctx2[(size_t)(s0 + s) * 512 + h2]);
            const float a = at[s0 + s];
            acc.x += a * c.x; acc.y += a * c.y;
        }
        px[t] = acc;
        __syncthreads();
        if (t < 512) {
            float2 w0 = px[t], w1 = px[t + 512];
            wcs[2 * t]     = w0.x + w1.x;
            wcs[2 * t + 1] = w0.y + w1.y;
        }
        __syncthreads();
    }
    {
        const __half2* cov2 = (const __half2*)(g_covh + (size_t)b * SV * COVV);
        const int c2 = t & 127, grp = t >> 7;
        float2 acc = make_float2(0.f, 0.f);
        const int s0 = grp * 64;
        #pragma unroll 8
        for (int s = 0; s < 64; ++s) {
            float2 c = __half22float2(cov2[(size_t)(s0 + s) * 128 + c2]);
            const float a = at[s0 + s];
            acc.x += a * c.x; acc.y += a * c.y;
        }
        px[t] = acc;
        __syncthreads();
        if (t < 128) {
            float2 s2 = make_float2(0.f, 0.f);
            #pragma unroll
            for (int g = 0; g < 8; ++g) {
                float2 p = px[t + 128 * g];
                s2.x += p.x; s2.y += p.y;
            }
            ac[2 * t] = s2.x; ac[2 * t + 1] = s2.y;
        }
        __syncthreads();
    }
    {
        const int d = t;
        float e2 = 0.f;
        #pragma unroll 4
        for (int c = 0; c < COVV; ++c) e2 += ac[c] * g_wcovT[(size_t)c * DIMV + d];
        g_cat[(size_t)b * 2 * DIMV + d] = wcs[d] + b_cov[d] + e2;
        g_cat[(size_t)b * 2 * DIMV + DIMV + d] = h[b * DIMV + d];
    }
}

// ---------------- mega: rz (1024) | xn (512) | hn (512) | htilde (128) -----------
__global__ void __launch_bounds__(256, 2) mega_kernel(
    const float* __restrict__ b_hh, const float* __restrict__ W_out)
{
    extern __shared__ float sm[];
    const int bid = blockIdx.x;
    const uint32_t smb = smem_u32(sm);
    const int tid = threadIdx.x, lane = tid & 31, wid = tid >> 5;
    const int wm = wid & 1, wn = wid >> 1;
    float acc[4][4][4];

    if (bid < 1024) {
        const int cb = bid & 3, by = bid >> 2;
        const int row0 = by * 128, jb = cb * 128;
        Seg segs[3] = {
            { g_ctxh, DIMV, g_wihAh + (size_t)jb * DIMV, DIMV, 16 },
            { g_covh, COVV, g_M2h   + (size_t)jb * COVV, COVV, 4 },
            { g_covh, COVV, g_whhh  + (size_t)jb * COVV, COVV, 4 } };
        mma_pass(segs, 3, row0, smb, acc);
        FOR_ELEMS(
            const int j = jb + cl;
            x0 += g_hB[bI * G3 + j]     + at * g_wihC[j]     + g_bsum[j];
            x1 += g_hB[bI * G3 + j + 1] + at * g_wihC[j + 1] + g_bsum[j + 1];
            __half2 hv = __floats2half2_rn(x0, x1);
            *(__half2*)(g_rz + (size_t)row * 512 + j) = hv;
        );
    } else if (bid < 1536) {
        const int r = bid - 1024, cb = r & 1, by = r >> 1;
        const int row0 = by * 128, jb = 512 + cb * 128;
        Seg segs[2] = {
            { g_ctxh, DIMV, g_wihAh + (size_t)jb * DIMV, DIMV, 16 },
            { g_covh, COVV, g_M2h   + (size_t)jb * COVV, COVV, 4 } };
        mma_pass(segs, 2, row0, smb, acc);
        FOR_ELEMS(
            const int j = jb + cl;
            x0 += g_hB[bI * G3 + j]     + at * g_wihC[j]     + g_bsum[j];
            x1 += g_hB[bI * G3 + j + 1] + at * g_wihC[j + 1] + g_bsum[j + 1];
            __half2 hv = __floats2half2_rn(x0, x1);
            *(__half2*)(g_xn + (size_t)row * 256 + cb * 128 + cl) = hv;
        );
    } else if (bid < 2048) {
        const int r = bid - 1536, cb = r & 1, by = r >> 1;
        const int row0 = by * 128, jb = 512 + cb * 128;
        Seg segs[1] = { { g_covh, COVV, g_whhh + (size_t)jb * COVV, COVV, 4 } };
        mma_pass(segs, 1, row0, smb, acc);
        FOR_ELEMS(
            const int j = jb + cl;
            x0 += b_hh[j];
            x1 += b_hh[j + 1];
            __half2 hv = __floats2half2_rn(x0, x1);
            *(__half2*)(g_hn + (size_t)row * 256 + cb * 128 + cl) = hv;
        );
    } else {
        const int r = bid - 2048, bx = r & 7, bz = r >> 3;
        sgemm_core(g_cat, 2 * DIMV, W_out, 2 * DIMV, bz * 128, bz * 128 + 128,
                   0, bx * 128, DIMV, g_part + (size_t)bz * BV * DIMV, sm);
    }
}

// ---------------- gru (8192) + htilde reduce (64), merged -------------------------
__global__ void gru_red_kernel(const float* __restrict__ cov,
                               float* __restrict__ out_cov,
                               float* __restrict__ out_htilde)
{
    const int bid = blockIdx.x, tid = threadIdx.x;
    if (bid < 8192) {
        const int idx = bid * 256 + tid;
        const size_t row = (size_t)(idx >> 6);
        const int q = idx & 63;
        const __half2* rz2 = (const __half2*)(g_rz + row * 512);
        const __half2* xn2 = (const __half2*)(g_xn + row * 256);
        const __half2* hn2 = (const __half2*)(g_hn + row * 256);
        float2 r0 = __half22float2(rz2[2*q]),       r1 = __half22float2(rz2[2*q+1]);
        float2 z0 = __half22float2(rz2[128+2*q]),   z1 = __half22float2(rz2[128+2*q+1]);
        float2 x0 = __half22float2(xn2[2*q]),       x1 = __half22float2(xn2[2*q+1]);
        float2 h0 = __half22float2(hn2[2*q]),       h1 = __half22float2(hn2[2*q+1]);
        float4 c0 = *(const float4*)(cov + row * COVV + q * 4);
        float4 o;
        {
            float r = sigmf(r0.x), z = sigmf(z0.x);
            float n = tanhf(x0.x + r * h0.x);
            o.x = (1.f - z) * n + z * c0.x;
        }
        {
            float r = sigmf(r0.y), z = sigmf(z0.y);
            float n = tanhf(x0.y + r * h0.y);
            o.y = (1.f - z) * n + z * c0.y;
        }
        {
            float r = sigmf(r1.x), z = sigmf(z1.x);
            float n = tanhf(x1.x + r * h1.x);
            o.z = (1.f - z) * n + z * c0.z;
        }
        {
            float r = sigmf(r1.y), z = sigmf(z1.y);
            float n = tanhf(x1.y + r * h1.y);
            o.w = (1.f - z) * n + z * c0.w;
        }
        *(float4*)(out_cov + row * COVV + q * 4) = o;
    } else {
        const int i = (bid - 8192) * 256 + tid;       // 16384 f4 of htilde
        float4 s = make_float4(0.f, 0.f, 0.f, 0.f);
        for (int z = 0; z < 16; ++z) {
            float4 p = *(const float4*)(g_part + (size_t)z * 65536 + i * 4);
            s.x += p.x; s.y += p.y; s.z += p.z; s.w += p.w;
        }
        s.x = tanhf(s.x); s.y = tanhf(s.y); s.z = tanhf(s.z); s.w = tanhf(s.w);
        *(float4*)(out_htilde + i * 4) = s;
    }
}

// ---------------- launch -----------------------------------------------------------
extern "C" void kernel_launch(void* const* d_in, const int* in_sizes, int n_in,
                              void* d_out, int out_size)
{
    const float* h       = (const float*)d_in[0];
    const float* context = (const float*)d_in[1];
    const float* cov     = (const float*)d_in[2];
    const float* W_in    = (const float*)d_in[3];
    const float* W_out   = (const float*)d_in[4];
    const float* W_cov   = (const float*)d_in[5];
    const float* b_cov   = (const float*)d_in[6];
    const float* w_ih    = (const float*)d_in[7];
    const float* w_hh    = (const float*)d_in[8];
    const float* b_ih    = (const float*)d_in[9];
    const float* b_hh    = (const float*)d_in[10];
    const void*  mask    = d_in[11];

    float* out = (float*)d_out;
    float* out_htilde = out;
    float* out_attn   = out + BV * DIMV;
    float* out_cov    = out + BV * DIMV + ROWS;

    const int SMSZ = 3 * 2 * (int)TBYTES;   // 98304
    const int SMSG = 12800;
    cudaFuncSetAttribute(mega_kernel, cudaFuncAttributeMaxDynamicSharedMemorySize, SMSZ);

    prep_kernel<<<5121, 256>>>((const unsigned int*)mask, w_ih, w_hh, W_cov,
                               b_cov, b_ih, b_hh, cov);
    sgemm3_kernel<<<304, 256, SMSG>>>(h, W_in);
    reduce3_kernel<<<248, 256>>>();
    score_kernel<<<ROWS / 8, 256>>>(context, cov);
    softmax_fused<<<BV, 1024>>>(mask, h, b_cov, out_attn);
    mega_kernel<<<2176, 256, SMSZ>>>(b_hh, W_out);
    gru_red_kernel<<<8192 + 64, 256>>>(cov, out_cov, out_htilde);
}

// round 16
// speedup vs baseline: 1.1171x; 1.1171x over previous
#include <cuda_runtime.h>
#include <cuda_fp16.h>
#include <math.h>
#include <stdint.h>

#define BV    64
#define SV    512
#define DIMV  1024
#define COVV  256
#define ROWS  (BV*SV)
#define G3    768
#define XW    2049

// ---------------- scratch ----------------------------------------------------
__device__ __half g_rz[(size_t)ROWS * 512];
__device__ __half g_xn[(size_t)ROWS * 256];
__device__ __half g_hn[(size_t)ROWS * 256];
__device__ __half g_ctxh[(size_t)ROWS * DIMV];
__device__ __half g_covh[(size_t)ROWS * COVV];
__device__ float g_target[BV * DIMV];
__device__ float g_tproj[BV * COVV];
__device__ float g_hB[BV * G3];
__device__ __half g_wihAh[(size_t)G3 * DIMV];
__device__ float  g_wihAf[(size_t)G3 * DIMV];
__device__ float g_wihH[(size_t)G3 * DIMV];
__device__ __half g_whhh[(size_t)G3 * COVV];
__device__ float g_wcovT[(size_t)COVV * DIMV];
__device__ __half g_M2h[(size_t)G3 * COVV];
__device__ float g_wihC[G3];
__device__ float g_bsum[G3];    // bA + b_ih (+ b_hh for cols < 512)
__device__ float g_score[ROWS];
__device__ float g_attn[ROWS];
__device__ float g_cat[BV * 2 * DIMV];
__device__ float g_part[2490368];
__device__ int   g_maskmode;

#define P_TGT 0
#define P_HB  524288
#define P_M2  917504

// ---------------- PTX helpers -------------------------------------------------
__device__ __forceinline__ uint32_t smem_u32(const void* p) {
    uint32_t a;
    asm("{ .reg .u64 t; cvta.to.shared.u64 t, %1; cvt.u32.u64 %0, t; }" : "=r"(a) : "l"(p));
    return a;
}
__device__ __forceinline__ void cpasync16(uint32_t dst, const void* src) {
    asm volatile("cp.async.ca.shared.global [%0], [%1], 16;" :: "r"(dst), "l"(src));
}
#define CP_COMMIT() asm volatile("cp.async.commit_group;" ::: "memory")
#define CP_WAIT1()  asm volatile("cp.async.wait_group 1;" ::: "memory")

#define LDSM4(r0,r1,r2,r3,addr) \
    asm volatile("ldmatrix.sync.aligned.m8n8.x4.shared.b16 {%0,%1,%2,%3}, [%4];" \
        : "=r"(r0),"=r"(r1),"=r"(r2),"=r"(r3) : "r"(addr))

#define MMA16(d, a, b0v, b1v) \
    asm volatile("mma.sync.aligned.m16n8k16.row.col.f32.f16.f16.f32 " \
        "{%0,%1,%2,%3},{%4,%5,%6,%7},{%8,%9},{%0,%1,%2,%3};" \
        : "+f"((d)[0]),"+f"((d)[1]),"+f"((d)[2]),"+f"((d)[3]) \
        : "r"((a)[0]),"r"((a)[1]),"r"((a)[2]),"r"((a)[3]),"r"(b0v),"r"(b1v))

__device__ __forceinline__ uint32_t swz(uint32_t o) { return o ^ ((o >> 3) & 0x70u); }
__device__ __forceinline__ float sigmf(float x) { return 1.f / (1.f + __expf(-x)); }

// ---------------- fp16 GEMM machinery: 64-half K stages, SW128, seg list -------
#define TBYTES 16384u
struct Seg { const __half* A; int lda; const __half* B; int ldb; int n; };

__device__ __forceinline__ void load_stage_h(const __half* __restrict__ A, int lda,
                                             const __half* __restrict__ B, int ldb,
                                             uint32_t smb, int buf, int kloc,
                                             int row0, int tid)
{
    const uint32_t dA = smb + (uint32_t)buf * 2u * TBYTES;
    const uint32_t dB = dA + TBYTES;
    #pragma unroll
    for (int it = 0; it < 4; ++it) {
        const int id = it * 256 + tid;
        const int r = id >> 3, q = id & 7;
        const uint32_t so = swz((uint32_t)(r * 128 + q * 16));
        cpasync16(dA + so, A + (size_t)(row0 + r) * lda + (size_t)kloc * 64 + q * 8);
        cpasync16(dB + so, B + (size_t)r * ldb + (size_t)kloc * 64 + q * 8);
    }
    CP_COMMIT();
}

__device__ __forceinline__ void seg_fetch(const Seg* segs, int nseg, int buf, int s,
                                          uint32_t smb, int row0, int tid)
{
    int t = s;
    #pragma unroll 1
    for (int g = 0; g < nseg; ++g) {
        if (t < segs[g].n) {
            load_stage_h(segs[g].A, segs[g].lda, segs[g].B, segs[g].ldb,
                         smb, buf, t, row0, tid);
            return;
        }
        t -= segs[g].n;
    }
}

__device__ void mma_pass(const Seg* segs, int nseg, int row0, uint32_t smb,
                         float acc[4][4][4])
{
    const int tid = threadIdx.x, lane = tid & 31, wid = tid >> 5;
    const int wm = wid & 1, wn = wid >> 1;
    const int t8 = lane >> 3, r8 = lane & 7;
    uint32_t abase[4], bbase[2];
    #pragma unroll
    for (int m = 0; m < 4; ++m)
        abase[m] = (uint32_t)((wm * 64 + m * 16 + (t8 & 1) * 8 + r8) * 128 + (t8 >> 1) * 16);
    #pragma unroll
    for (int p = 0; p < 2; ++p)
        bbase[p] = (uint32_t)((wn * 32 + p * 16 + (t8 & 1) * 8 + r8) * 128 + (t8 >> 1) * 16);

    #pragma unroll
    for (int m = 0; m < 4; ++m)
        #pragma unroll
        for (int n = 0; n < 4; ++n)
            #pragma unroll
            for (int i = 0; i < 4; ++i) acc[m][n][i] = 0.f;

    int S = 0;
    for (int g = 0; g < nseg; ++g) S += segs[g].n;

    seg_fetch(segs, nseg, 0, 0, smb, row0, tid);
    seg_fetch(segs, nseg, 1, 1, smb, row0, tid);

    #pragma unroll 1
    for (int kt = 0; kt < S; ++kt) {
        CP_WAIT1();
        __syncthreads();
        if (kt + 2 < S) seg_fetch(segs, nseg, (kt + 2) % 3, kt + 2, smb, row0, tid);
        const uint32_t stg = smb + (uint32_t)(kt % 3) * 2u * TBYTES;

        #pragma unroll
        for (int ks = 0; ks < 4; ++ks) {
            uint32_t ah[4][4], bh[4][2];
            #pragma unroll
            for (int m = 0; m < 4; ++m)
                LDSM4(ah[m][0], ah[m][1], ah[m][2], ah[m][3],
                      stg + swz(abase[m] + (uint32_t)ks * 32u));
            #pragma unroll
            for (int p = 0; p < 2; ++p) {
                uint32_t x0, x1, x2, x3;
                LDSM4(x0, x1, x2, x3, stg + TBYTES + swz(bbase[p] + (uint32_t)ks * 32u));
                bh[2 * p + 0][0] = x0; bh[2 * p + 0][1] = x2;
                bh[2 * p + 1][0] = x1; bh[2 * p + 1][1] = x3;
            }
            #pragma unroll
            for (int m = 0; m < 4; ++m)
                #pragma unroll
                for (int n = 0; n < 4; ++n)
                    MMA16(acc[m][n], ah[m], bh[n][0], bh[n][1]);
        }
    }
}

#define FOR_ELEMS(...)                                                          \
    {                                                                           \
        const int g2 = lane >> 2, tg = lane & 3;                                \
        _Pragma("unroll")                                                       \
        for (int m = 0; m < 4; ++m)                                             \
        _Pragma("unroll")                                                       \
        for (int h2 = 0; h2 < 2; ++h2) {                                        \
            const int row = row0 + wm * 64 + m * 16 + h2 * 8 + g2;              \
            const int bI = row >> 9;                                            \
            const float at = g_attn[row];                                       \
            (void)bI; (void)at;                                                 \
            _Pragma("unroll")                                                   \
            for (int nn = 0; nn < 4; ++nn) {                                    \
                const int cl = wn * 32 + nn * 8 + 2 * tg;                       \
                float x0 = acc[m][nn][h2 * 2 + 0];                              \
                float x1 = acc[m][nn][h2 * 2 + 1];                              \
                __VA_ARGS__                                                     \
            }                                                                   \
        }                                                                       \
    }

// ---------------- split-K fp32 SGEMM core --------------------------------------
__device__ void sgemm_core(
    const float* __restrict__ X, int ldx,
    const float* __restrict__ W, int ldw,
    int k0, int k1, int row0, int col0, int N,
    float* __restrict__ partz, float* sm)
{
    float* Xs = sm;
    float* Ws = sm + 1088;
    const int tid = threadIdx.x;
    const int tr = tid >> 5, tc = tid & 31;
    float acc[8][4];
    #pragma unroll
    for (int i = 0; i < 8; ++i)
        #pragma unroll
        for (int j = 0; j < 4; ++j) acc[i][j] = 0.f;

    const int xr = tid >> 2, xk = (tid & 3) * 4;
    for (int kt = k0; kt < k1; kt += 16) {
        float4 xv = *(const float4*)(X + (size_t)(row0 + xr) * ldx + kt + xk);
        Xs[(xk+0)*68+xr] = xv.x; Xs[(xk+1)*68+xr] = xv.y;
        Xs[(xk+2)*68+xr] = xv.z; Xs[(xk+3)*68+xr] = xv.w;
        #pragma unroll
        for (int w2 = 0; w2 < 2; ++w2) {
            const int r = xr + w2 * 64;
            float4 wv = *(const float4*)(W + (size_t)(col0 + r) * ldw + kt + xk);
            Ws[(xk+0)*132+r] = wv.x; Ws[(xk+1)*132+r] = wv.y;
            Ws[(xk+2)*132+r] = wv.z; Ws[(xk+3)*132+r] = wv.w;
        }
        __syncthreads();
        #pragma unroll
        for (int kk = 0; kk < 16; ++kk) {
            float a[8], bb[4];
            #pragma unroll
            for (int i = 0; i < 8; ++i) a[i] = Xs[kk*68 + tr * 8 + i];
            #pragma unroll
            for (int j = 0; j < 4; ++j) bb[j] = Ws[kk*132 + tc * 4 + j];
            #pragma unroll
            for (int i = 0; i < 8; ++i)
                #pragma unroll
                for (int j = 0; j < 4; ++j) acc[i][j] += a[i] * bb[j];
        }
        __syncthreads();
    }
    #pragma unroll
    for (int i = 0; i < 8; ++i)
        *(float4*)(partz + (size_t)(row0 + tr * 8 + i) * N + col0 + tc * 4)
            = make_float4(acc[i][0], acc[i][1], acc[i][2], acc[i][3]);
}

__global__ void __launch_bounds__(256) sgemm3_kernel(
    const float* __restrict__ h, const float* __restrict__ W_in)
{
    extern __shared__ float sm[];
    const int bid = blockIdx.x;
    if (bid < 64) {
        const int bx = bid & 7, bz = bid >> 3;
        sgemm_core(h, DIMV, W_in, DIMV, bz * 128, bz * 128 + 128,
                   0, bx * 128, DIMV, g_part + P_TGT + (size_t)bz * BV * DIMV, sm);
    } else if (bid < 112) {
        const int r = bid - 64, bx = r % 6, bz = r / 6;
        sgemm_core(h, DIMV, g_wihH, DIMV, bz * 128, bz * 128 + 128,
                   0, bx * 128, G3, g_part + P_HB + (size_t)bz * BV * G3, sm);
    } else {
        const int r = bid - 112;
        const int bx = r & 1, by = (r >> 1) % 12, bz = r / 24;
        sgemm_core(g_wihAf, DIMV, g_wcovT, DIMV, bz * 128, bz * 128 + 128,
                   by * 64, bx * 128, COVV, g_part + P_M2 + (size_t)bz * G3 * COVV, sm);
    }
}

__global__ void reduce3_kernel()
{
    const int i = blockIdx.x * 256 + threadIdx.x;
    const float* part; int ii, MN4, F = 0;
    float* outf = nullptr;
    if (i < 16384)       { ii = i;         MN4 = 16384; part = g_part + P_TGT; outf = g_target; }
    else if (i < 28672)  { ii = i - 16384; MN4 = 12288; part = g_part + P_HB;  outf = g_hB; }
    else if (i < 77824)  { ii = i - 28672; MN4 = 49152; part = g_part + P_M2;  F = 2; }
    else return;
    float4 s = make_float4(0.f, 0.f, 0.f, 0.f);
    for (int z = 0; z < 8; ++z) {
        float4 p = *(const float4*)(part + (size_t)z * MN4 * 4 + ii * 4);
        s.x += p.x; s.y += p.y; s.z += p.z; s.w += p.w;
    }
    if (F == 2) {
        __half2 h0 = __floats2half2_rn(s.x, s.y);
        __half2 h1 = __floats2half2_rn(s.z, s.w);
        uint2 o; o.x = *(uint32_t*)&h0; o.y = *(uint32_t*)&h1;
        *(uint2*)(g_M2h + (size_t)ii * 4) = o;
    } else {
        *(float4*)(outf + ii * 4) = s;
    }
}

// ---------------- prologue: mask detect | repack | cov->fp16 --------------------
__global__ void prep_kernel(const unsigned int* __restrict__ mask,
                            const float* __restrict__ w_ih,
                            const float* __restrict__ w_hh,
                            const float* __restrict__ W_cov,
                            const float* __restrict__ b_cov,
                            const float* __restrict__ b_ih,
                            const float* __restrict__ b_hh,
                            const float* __restrict__ cov)
{
    const int bid = blockIdx.x, tid = threadIdx.x;
    if (bid == 0) {
        __shared__ int notint, notfloat;
        if (tid == 0) { notint = 0; notfloat = 0; }
        __syncthreads();
        int li = 0, lf = 0;
        for (int i = tid; i < 8192; i += 256) {
            unsigned v = mask[i];
            if (v > 1u) li = 1;
            if (v != 0u && v != 0x3F800000u) lf = 1;
        }
        if (li) notint = 1;
        if (lf) notfloat = 1;
        __syncthreads();
        if (tid == 0) g_maskmode = (!notint) ? 0 : ((!notfloat) ? 1 : 2);
        return;
    }
    if (bid <= 1024) {
        const int j = bid - 1;
        if (j < G3) {
            __shared__ float red[256];
            float pa = 0.f;
            for (int k = tid; k < DIMV; k += 256) {
                float a = w_ih[(size_t)j * XW + k];
                __half ah = __float2half_rn(a);
                g_wihAh[(size_t)j * DIMV + k] = ah;
                g_wihAf[(size_t)j * DIMV + k] = __half2float(ah);
                g_wihH[(size_t)j * DIMV + k] = w_ih[(size_t)j * XW + DIMV + k];
                pa += a * b_cov[k];
            }
            if (tid < COVV)
                g_whhh[(size_t)j * COVV + tid] = __float2half_rn(w_hh[(size_t)j * COVV + tid]);
            red[tid] = pa; __syncthreads();
            for (int o = 128; o > 0; o >>= 1) { if (tid < o) red[tid] += red[tid + o]; __syncthreads(); }
            if (tid == 0) {
                float bs = red[0] + b_ih[j];
                if (j < 512) bs += b_hh[j];
                g_bsum[j] = bs;
                g_wihC[j] = w_ih[(size_t)j * XW + 2 * DIMV];
            }
        } else {
            const int c = j - G3;
            for (int d = tid; d < DIMV; d += 256)
                g_wcovT[(size_t)c * DIMV + d] = W_cov[(size_t)d * COVV + c];
        }
        return;
    }
    const int i = (bid - 1025) * 256 + tid;
    const size_t off = (size_t)i * 8;
    float4 a = *(const float4*)(cov + off);
    float4 b = *(const float4*)(cov + off + 4);
    __half2 h0 = __floats2half2_rn(a.x, a.y);
    __half2 h1 = __floats2half2_rn(a.z, a.w);
    __half2 h2 = __floats2half2_rn(b.x, b.y);
    __half2 h3 = __floats2half2_rn(b.z, b.w);
    uint4 o;
    o.x = *(uint32_t*)&h0; o.y = *(uint32_t*)&h1;
    o.z = *(uint32_t*)&h2; o.w = *(uint32_t*)&h3;
    *(uint4*)(g_covh + off) = o;
}

// ---------------- tproj = target @ W_cov ------------------------------------------
__global__ void __launch_bounds__(256) tproj_kernel()
{
    __shared__ float wc[DIMV];
    const int c = blockIdx.x, tid = threadIdx.x;
    for (int i = tid; i < DIMV; i += 256) wc[i] = g_wcovT[(size_t)c * DIMV + i];
    __syncthreads();
    const int w = tid >> 5, lane = tid & 31;
    for (int b = w; b < BV; b += 8) {
        const float4* tg = (const float4*)(g_target + (size_t)b * DIMV);
        float s = 0.f;
        #pragma unroll
        for (int i = 0; i < 8; ++i) {
            float4 t4 = tg[lane + i * 32];
            const float* w4 = wc + (lane + i * 32) * 4;
            s += t4.x * w4[0] + t4.y * w4[1] + t4.z * w4[2] + t4.w * w4[3];
        }
        #pragma unroll
        for (int o = 16; o; o >>= 1) s += __shfl_xor_sync(0xffffffffu, s, o);
        if (lane == 0) g_tproj[b * COVV + c] = s;
    }
}

// ---------------- exact scores + fused ctx->fp16 ----------------------------------
__global__ void score_kernel(const float* __restrict__ context,
                             const float* __restrict__ cov)
{
    const int r = blockIdx.x * 8 + (threadIdx.x >> 5);
    const int lane = threadIdx.x & 31;
    const int b = r >> 9;
    const float4* ct = (const float4*)(context + (size_t)r * DIMV);
    const float4* tg = (const float4*)(g_target + (size_t)b * DIMV);
    float s = 0.f;
    #pragma unroll
    for (int i = 0; i < 8; ++i) {
        float4 c4 = ct[lane + i * 32], t4 = tg[lane + i * 32];
        s += c4.x * t4.x + c4.y * t4.y + c4.z * t4.z + c4.w * t4.w;
        __half2 p0 = __floats2half2_rn(c4.x, c4.y);
        __half2 p1 = __floats2half2_rn(c4.z, c4.w);
        uint2 o; o.x = *(uint32_t*)&p0; o.y = *(uint32_t*)&p1;
        *(uint2*)(g_ctxh + (size_t)r * DIMV + (size_t)(lane + i * 32) * 4) = o;
    }
    const float4* cv = (const float4*)(cov + (size_t)r * COVV);
    const float4* tp = (const float4*)(g_tproj + (size_t)b * COVV);
    #pragma unroll
    for (int i = 0; i < 2; ++i) {
        float4 c4 = cv[lane + i * 32], t4 = tp[lane + i * 32];
        s += c4.x * t4.x + c4.y * t4.y + c4.z * t4.z + c4.w * t4.w;
    }
    #pragma unroll
    for (int o = 16; o; o >>= 1) s += __shfl_xor_sync(0xffffffffu, s, o);
    if (lane == 0) g_score[r] = s;
}

// ---------------- fused softmax + wc + aco + cat ----------------------------------
__global__ void __launch_bounds__(1024) softmax_fused(
    const void* __restrict__ mask,
    const float* __restrict__ h, const float* __restrict__ b_cov,
    float* __restrict__ out_attn)
{
    const int b = blockIdx.x, t = threadIdx.x;
    __shared__ float at[SV];
    __shared__ float red[SV];
    __shared__ float2 px[1024];
    __shared__ float wcs[DIMV];
    __shared__ float ac[COVV];

    const int mode = g_maskmode;
    float sc = 0.f; bool masked = false;
    if (t < SV) {
        const int idx = b * SV + t;
        if (mode == 0)      masked = ((const int*)mask)[idx] != 0;
        else if (mode == 1) masked = ((const float*)mask)[idx] != 0.0f;
        else                masked = ((const unsigned char*)mask)[idx] != 0;
        sc = masked ? -INFINITY : g_score[idx];
        red[t] = sc;
    }
    __syncthreads();
    for (int o = 256; o > 0; o >>= 1) {
        if (t < o) red[t] = fmaxf(red[t], red[t + o]);
        __syncthreads();
    }
    const float m = red[0];
    __syncthreads();
    float e = 0.f;
    if (t < SV) { e = masked ? 0.f : __expf(sc - m); red[t] = e; }
    __syncthreads();
    for (int o = 256; o > 0; o >>= 1) {
        if (t < o) red[t] += red[t + o];
        __syncthreads();
    }
    const float inv = 1.f / red[0];
    if (t < SV) {
        const float a = e * inv;
        at[t] = a;
        g_attn[b * SV + t] = a;
        out_attn[b * SV + t] = a;
    }
    __syncthreads();

    {
        const __half2* ctx2 = (const __half2*)(g_ctxh + (size_t)b * SV * DIMV);
        const int h2 = t & 511, grp = t >> 9;
        float2 acc = make_float2(0.f, 0.f);
        const int s0 = grp * 256;
        #pragma unroll 8
        for (int s = 0; s < 256; ++s) {
            float2 c = __half22float2(ctx2[(size_t)(s0 + s) * 512 + h2]);
            const float a = at[s0 + s];
            acc.x += a * c.x; acc.y += a * c.y;
        }
        px[t] = acc;
        __syncthreads();
        if (t < 512) {
            float2 w0 = px[t], w1 = px[t + 512];
            wcs[2 * t]     = w0.x + w1.x;
            wcs[2 * t + 1] = w0.y + w1.y;
        }
        __syncthreads();
    }
    {
        const __half2* cov2 = (const __half2*)(g_covh + (size_t)b * SV * COVV);
        const int c2 = t & 127, grp = t >> 7;
        float2 acc = make_float2(0.f, 0.f);
        const int s0 = grp * 64;
        #pragma unroll 8
        for (int s = 0; s < 64; ++s) {
            float2 c = __half22float2(cov2[(size_t)(s0 + s) * 128 + c2]);
            const float a = at[s0 + s];
            acc.x += a * c.x; acc.y += a * c.y;
        }
        px[t] = acc;
        __syncthreads();
        if (t < 128) {
            float2 s2 = make_float2(0.f, 0.f);
            #pragma unroll
            for (int g = 0; g < 8; ++g) {
                float2 p = px[t + 128 * g];
                s2.x += p.x; s2.y += p.y;
            }
            ac[2 * t] = s2.x; ac[2 * t + 1] = s2.y;
        }
        __syncthreads();
    }
    {
        const int d = t;
        float e2 = 0.f;
        #pragma unroll 4
        for (int c = 0; c < COVV; ++c) e2 += ac[c] * g_wcovT[(size_t)c * DIMV + d];
        g_cat[(size_t)b * 2 * DIMV + d] = wcs[d] + b_cov[d] + e2;
        g_cat[(size_t)b * 2 * DIMV + DIMV + d] = h[b * DIMV + d];
    }
}

// ---------------- mega: rz (1024) | xn (512) | hn (512) | htilde (128) ------------
__global__ void __launch_bounds__(256, 2) mega_kernel(
    const float* __restrict__ b_hh, const float* __restrict__ W_out)
{
    extern __shared__ float sm[];
    const int bid = blockIdx.x;
    const uint32_t smb = smem_u32(sm);
    const int tid = threadIdx.x, lane = tid & 31, wid = tid >> 5;
    const int wm = wid & 1, wn = wid >> 1;
    float acc[4][4][4];

    if (bid < 1024) {
        const int cb = bid & 3, by = bid >> 2;
        const int row0 = by * 128, jb = cb * 128;
        Seg segs[3] = {
            { g_ctxh, DIMV, g_wihAh + (size_t)jb * DIMV, DIMV, 16 },
            { g_covh, COVV, g_M2h   + (size_t)jb * COVV, COVV, 4 },
            { g_covh, COVV, g_whhh  + (size_t)jb * COVV, COVV, 4 } };
        mma_pass(segs, 3, row0, smb, acc);
        FOR_ELEMS(
            const int j = jb + cl;
            x0 += g_hB[bI * G3 + j]     + at * g_wihC[j]     + g_bsum[j];
            x1 += g_hB[bI * G3 + j + 1] + at * g_wihC[j + 1] + g_bsum[j + 1];
            __half2 hv = __floats2half2_rn(x0, x1);
            *(__half2*)(g_rz + (size_t)row * 512 + j) = hv;
        );
    } else if (bid < 1536) {
        const int r = bid - 1024, cb = r & 1, by = r >> 1;
        const int row0 = by * 128, jb = 512 + cb * 128;
        Seg segs[2] = {
            { g_ctxh, DIMV, g_wihAh + (size_t)jb * DIMV, DIMV, 16 },
            { g_covh, COVV, g_M2h   + (size_t)jb * COVV, COVV, 4 } };
        mma_pass(segs, 2, row0, smb, acc);
        FOR_ELEMS(
            const int j = jb + cl;
            x0 += g_hB[bI * G3 + j]     + at * g_wihC[j]     + g_bsum[j];
            x1 += g_hB[bI * G3 + j + 1] + at * g_wihC[j + 1] + g_bsum[j + 1];
            __half2 hv = __floats2half2_rn(x0, x1);
            *(__half2*)(g_xn + (size_t)row * 256 + cb * 128 + cl) = hv;
        );
    } else if (bid < 2048) {
        const int r = bid - 1536, cb = r & 1, by = r >> 1;
        const int row0 = by * 128, jb = 512 + cb * 128;
        Seg segs[1] = { { g_covh, COVV, g_whhh + (size_t)jb * COVV, COVV, 4 } };
        mma_pass(segs, 1, row0, smb, acc);
        FOR_ELEMS(
            const int j = jb + cl;
            x0 += b_hh[j];
            x1 += b_hh[j + 1];
            __half2 hv = __floats2half2_rn(x0, x1);
            *(__half2*)(g_hn + (size_t)row * 256 + cb * 128 + cl) = hv;
        );
    } else {
        const int r = bid - 2048, bx = r & 7, bz = r >> 3;
        sgemm_core(g_cat, 2 * DIMV, W_out, 2 * DIMV, bz * 128, bz * 128 + 128,
                   0, bx * 128, DIMV, g_part + (size_t)bz * BV * DIMV, sm);
    }
}

// ---------------- gru (8192) + htilde reduce (64), merged -------------------------
__global__ void gru_red_kernel(const float* __restrict__ cov,
                               float* __restrict__ out_cov,
                               float* __restrict__ out_htilde)
{
    const int bid = blockIdx.x, tid = threadIdx.x;
    if (bid < 8192) {
        const int idx = bid * 256 + tid;
        const size_t row = (size_t)(idx >> 6);
        const int q = idx & 63;
        const __half2* rz2 = (const __half2*)(g_rz + row * 512);
        const __half2* xn2 = (const __half2*)(g_xn + row * 256);
        const __half2* hn2 = (const __half2*)(g_hn + row * 256);
        float2 r0 = __half22float2(rz2[2*q]),       r1 = __half22float2(rz2[2*q+1]);
        float2 z0 = __half22float2(rz2[128+2*q]),   z1 = __half22float2(rz2[128+2*q+1]);
        float2 x0 = __half22float2(xn2[2*q]),       x1 = __half22float2(xn2[2*q+1]);
        float2 h0 = __half22float2(hn2[2*q]),       h1 = __half22float2(hn2[2*q+1]);
        float4 c0 = *(const float4*)(cov + row * COVV + q * 4);
        float4 o;
        {
            float r = sigmf(r0.x), z = sigmf(z0.x);
            float n = tanhf(x0.x + r * h0.x);
            o.x = (1.f - z) * n + z * c0.x;
        }
        {
            float r = sigmf(r0.y), z = sigmf(z0.y);
            float n = tanhf(x0.y + r * h0.y);
            o.y = (1.f - z) * n + z * c0.y;
        }
        {
            float r = sigmf(r1.x), z = sigmf(z1.x);
            float n = tanhf(x1.x + r * h1.x);
            o.z = (1.f - z) * n + z * c0.z;
        }
        {
            float r = sigmf(r1.y), z = sigmf(z1.y);
            float n = tanhf(x1.y + r * h1.y);
            o.w = (1.f - z) * n + z * c0.w;
        }
        *(float4*)(out_cov + row * COVV + q * 4) = o;
    } else {
        const int i = (bid - 8192) * 256 + tid;       // 16384 f4 of htilde
        float4 s = make_float4(0.f, 0.f, 0.f, 0.f);
        for (int z = 0; z < 16; ++z) {
            float4 p = *(const float4*)(g_part + (size_t)z * 65536 + i * 4);
            s.x += p.x; s.y += p.y; s.z += p.z; s.w += p.w;
        }
        s.x = tanhf(s.x); s.y = tanhf(s.y); s.z = tanhf(s.z); s.w = tanhf(s.w);
        *(float4*)(out_htilde + i * 4) = s;
    }
}

// ---------------- launch -----------------------------------------------------------
extern "C" void kernel_launch(void* const* d_in, const int* in_sizes, int n_in,
                              void* d_out, int out_size)
{
    const float* h       = (const float*)d_in[0];
    const float* context = (const float*)d_in[1];
    const float* cov     = (const float*)d_in[2];
    const float* W_in    = (const float*)d_in[3];
    const float* W_out   = (const float*)d_in[4];
    const float* W_cov   = (const float*)d_in[5];
    const float* b_cov   = (const float*)d_in[6];
    const float* w_ih    = (const float*)d_in[7];
    const float* w_hh    = (const float*)d_in[8];
    const float* b_ih    = (const float*)d_in[9];
    const float* b_hh    = (const float*)d_in[10];
    const void*  mask    = d_in[11];

    float* out = (float*)d_out;
    float* out_htilde = out;
    float* out_attn   = out + BV * DIMV;
    float* out_cov    = out + BV * DIMV + ROWS;

    const int SMSZ = 3 * 2 * (int)TBYTES;   // 98304
    const int SMSG = 12800;
    cudaFuncSetAttribute(mega_kernel, cudaFuncAttributeMaxDynamicSharedMemorySize, SMSZ);

    prep_kernel<<<5121, 256>>>((const unsigned int*)mask, w_ih, w_hh, W_cov,
                               b_cov, b_ih, b_hh, cov);
    sgemm3_kernel<<<304, 256, SMSG>>>(h, W_in);
    reduce3_kernel<<<304, 256>>>();
    tproj_kernel<<<COVV, 256>>>();
    score_kernel<<<ROWS / 8, 256>>>(context, cov);
    softmax_fused<<<BV, 1024>>>(mask, h, b_cov, out_attn);
    mega_kernel<<<2176, 256, SMSZ>>>(b_hh, W_out);
    gru_red_kernel<<<8192 + 64, 256>>>(cov, out_cov, out_htilde);
}